// round 15
// baseline (speedup 1.0000x reference)
#include <cuda_runtime.h>
#include <math.h>
#include <stdint.h>

#define B_  64
#define N_  512
#define C_  768
#define H_  12
#define HD  64
#define QS  ((size_t)B_ * H_ * N_ * HD)

// Scratch (allocation-free contract -> __device__ globals)
__device__ __align__(16) float g_qkv[3 * QS];                 // Q,K:[b,h,n,d]  V:[b,h,d,n]
__device__ __align__(16) float g_att[(size_t)B_ * N_ * C_];   // attention out (tf32-rounded)

// ---------------------------------------------------------------------------
__device__ __forceinline__ unsigned f2tf32(float f) {
    unsigned r;
    asm("cvt.rna.tf32.f32 %0, %1;" : "=r"(r) : "f"(f));
    return r;
}
__device__ __forceinline__ float f2tf32f(float f) { return __uint_as_float(f2tf32(f)); }

__device__ __forceinline__ void mma_tf32(float c[4],
                                         unsigned a0, unsigned a1, unsigned a2, unsigned a3,
                                         unsigned b0, unsigned b1) {
    asm volatile(
        "mma.sync.aligned.m16n8k8.row.col.f32.tf32.tf32.f32 "
        "{%0,%1,%2,%3}, {%4,%5,%6,%7}, {%8,%9}, {%0,%1,%2,%3};"
        : "+f"(c[0]), "+f"(c[1]), "+f"(c[2]), "+f"(c[3])
        : "r"(a0), "r"(a1), "r"(a2), "r"(a3), "r"(b0), "r"(b1));
}

__device__ __forceinline__ void cp_async16(unsigned dst, const void* src) {
    asm volatile("cp.async.ca.shared.global [%0], [%1], 16;" :: "r"(dst), "l"(src));
}
__device__ __forceinline__ void cp_commit() { asm volatile("cp.async.commit_group;"); }
template<int NW>
__device__ __forceinline__ void cp_wait() {
    asm volatile("cp.async.wait_group %0;" :: "n"(NW));
}

// ---------------------------------------------------------------------------
// tf32 GEMM v5: out = A[M,K] @ W[N,K]^T. CTA 128x128, 256 threads = 8 warps
// (2 M x 4 N), warp tile 64x32. BK=32, THREE-stage cp.async pipeline with a
// SINGLE __syncthreads per chunk (24 barriers vs 48 in v4).
// Safety: stage(s+2) writes buffer (s-1)%3; every warp reaches the iter-s
// barrier only after finishing compute s-1, so no reuse race.
// MODE 0: x @ qkv_w^T -> scatter g_qkv (V transposed). MODE 1: g_att @ proj_w^T + bias.
// ---------------------------------------------------------------------------
#define GST 36
#define GBUF (128 * GST)
#define SMEM_GEMM (6 * GBUF * 4)     // 3 bufs x (A + B) = 110592 B

template<int MODE>
__global__ __launch_bounds__(256, 2)
void gemm_tf32(const float* __restrict__ A,
               const float* __restrict__ W,
               const float* __restrict__ bias,
               float* __restrict__ out)
{
    extern __shared__ float smg[];
    float* As = smg;                 // [3][128][36]
    float* Ws = smg + 3 * GBUF;      // [3][128][36]
    const int K = C_;

    const float* Ap = (MODE == 1) ? (const float*)g_att : A;

    int m0 = blockIdx.y * 128;
    int n0 = blockIdx.x * 128;
    int tid = threadIdx.x;
    int lane = tid & 31, warp = tid >> 5;
    int wm = warp & 1;            // 2 M-halves of 64
    int wn = warp >> 1;           // 4 N-quarters of 32
    int g = lane >> 2, t = lane & 3;

    unsigned sbase = (unsigned)__cvta_generic_to_shared(smg);

    float acc[4][4][4];
#pragma unroll
    for (int mt = 0; mt < 4; mt++)
#pragma unroll
        for (int nt = 0; nt < 4; nt++)
#pragma unroll
            for (int r = 0; r < 4; r++) acc[mt][nt][r] = 0.f;

    int lr = tid >> 3;            // 0..31
    int lkq = (tid & 7) * 4;      // 0..28

    const int NS = K / 32;        // 24

    auto stage = [&](int s, int buf) {
        int k0 = s * 32;
#pragma unroll
        for (int p = 0; p < 4; p++) {
            int r = p * 32 + lr;
            unsigned dA = sbase + (unsigned)((buf * GBUF + r * GST + lkq) * 4);
            unsigned dW = sbase + (unsigned)((3 * GBUF + buf * GBUF + r * GST + lkq) * 4);
            cp_async16(dA, Ap + (size_t)(m0 + r) * K + k0 + lkq);
            cp_async16(dW, W  + (size_t)(n0 + r) * K + k0 + lkq);
        }
    };

    stage(0, 0); cp_commit();
    stage(1, 1); cp_commit();

    for (int s = 0; s < NS; s++) {
        // invariant: pending groups at top = {s, s+1} (that exist)
        if (s + 1 < NS) cp_wait<1>(); else cp_wait<0>();
        __syncthreads();                       // buffer s ready for ALL threads;
                                               // all warps done computing s-1
        if (s + 2 < NS) { stage(s + 2, (s + 2) % 3); cp_commit(); }

        const float* Ab = As + (s % 3) * GBUF;
        const float* Wb = Ws + (s % 3) * GBUF;

#pragma unroll
        for (int kb = 0; kb < 32; kb += 8) {
            unsigned a[4][4];
#pragma unroll
            for (int mt = 0; mt < 4; mt++) {
                int r = wm * 64 + mt * 16 + g;
                a[mt][0] = f2tf32(Ab[r * GST + kb + t]);
                a[mt][1] = f2tf32(Ab[(r + 8) * GST + kb + t]);
                a[mt][2] = f2tf32(Ab[r * GST + kb + t + 4]);
                a[mt][3] = f2tf32(Ab[(r + 8) * GST + kb + t + 4]);
            }
#pragma unroll
            for (int nt = 0; nt < 4; nt++) {
                int c = wn * 32 + nt * 8 + g;
                unsigned b0 = f2tf32(Wb[c * GST + kb + t]);
                unsigned b1 = f2tf32(Wb[c * GST + kb + t + 4]);
#pragma unroll
                for (int mt = 0; mt < 4; mt++)
                    mma_tf32(acc[mt][nt], a[mt][0], a[mt][1], a[mt][2], a[mt][3], b0, b1);
            }
        }
    }

    // epilogue: c-frag rows g,g+8; cols 2t,2t+1
#pragma unroll
    for (int mt = 0; mt < 4; mt++) {
#pragma unroll
        for (int nt = 0; nt < 4; nt++) {
            int n = n0 + wn * 32 + nt * 8 + 2 * t;
#pragma unroll
            for (int half = 0; half < 2; half++) {
                int m = m0 + wm * 64 + mt * 16 + g + half * 8;
                float2 val = make_float2(acc[mt][nt][half * 2],
                                         acc[mt][nt][half * 2 + 1]);
                if (MODE == 0) {
                    int which = n / C_;
                    int rem = n - which * C_;
                    int h = rem >> 6;
                    int d = rem & 63;
                    int b = m >> 9;
                    int nn = m & 511;
                    if (which < 2) {
                        float* dst = g_qkv + (size_t)which * QS
                                   + (((size_t)(b * H_ + h) * N_ + nn) * HD) + d;
                        *(float2*)dst = val;
                    } else {
                        // V transposed: [b][h][d][n]
                        float* dst = g_qkv + 2 * QS
                                   + ((size_t)(b * H_ + h) * HD + d) * N_ + nn;
                        dst[0] = val.x;
                        dst[N_] = val.y;
                    }
                } else {
                    val.x += bias[n];
                    val.y += bias[n + 1];
                    *(float2*)(out + (size_t)m * C_ + n) = val;
                }
            }
        }
    }
}

// ---------------------------------------------------------------------------
// tf32 tensor-core flash attention v2: q-tile 128 rows, 256 threads = 8 warps,
// each warp owns 16 q-rows. K/V tile loads + cvts + bias amortize over 2x MMAs.
// Per-warp math identical to the proven v1.
// ---------------------------------------------------------------------------
#define AST 68
#define SMEM_ATTN ((64 * AST + 64 * AST + 128 * AST + 192) * 4)   // 70400 B

__global__ __launch_bounds__(256)
void attn_kernel(const float* __restrict__ bias_table)
{
    const int ST = AST;
    extern __shared__ float sm[];
    float* Ks  = sm;                // [64][68]   Ks[key][d]
    float* Vs  = Ks + 64 * ST;      // [64][68]   Vs[d][key]
    float* Ps  = Vs + 64 * ST;      // [128][68]  Ps[q][key]; also Q staging
    float* bsh = Ps + 128 * ST;     // [192]

    int bh = blockIdx.y;
    int b = bh / H_;
    int h = bh - b * H_;
    int i0 = blockIdx.x * 128;

    const float* qb  = g_qkv + (size_t)bh * N_ * HD;
    const float* kgb = qb + QS;
    const float* vbt = g_qkv + 2 * QS + (size_t)bh * HD * N_;  // [d][n]

    int tid = threadIdx.x;
    int lane = tid & 31, warp = tid >> 5;
    int g = lane >> 2, t = lane & 3;
    int q0 = warp * 16;             // 0..112

    // stage 128 Q rows into Ps
    for (int i = tid; i < 2048; i += 256) {
        int r = i >> 4, dq = (i & 15) * 4;
        *(float4*)&Ps[r * ST + dq] = *(const float4*)(qb + (size_t)(i0 + r) * HD + dq);
    }
    __syncthreads();

    unsigned qa[8][4];
#pragma unroll
    for (int kb = 0; kb < 8; kb++) {
        qa[kb][0] = f2tf32(0.125f * Ps[(q0 + g) * ST + kb * 8 + t]);
        qa[kb][1] = f2tf32(0.125f * Ps[(q0 + g + 8) * ST + kb * 8 + t]);
        qa[kb][2] = f2tf32(0.125f * Ps[(q0 + g) * ST + kb * 8 + t + 4]);
        qa[kb][3] = f2tf32(0.125f * Ps[(q0 + g + 8) * ST + kb * 8 + t + 4]);
    }
    __syncthreads();

    float m_[2] = {-1e30f, -1e30f};
    float l_[2] = {0.f, 0.f};
    float o_[8][4];
#pragma unroll
    for (int nt = 0; nt < 8; nt++)
#pragma unroll
        for (int r = 0; r < 4; r++) o_[nt][r] = 0.f;

    for (int kt = 0; kt < 8; kt++) {
        for (int i = tid; i < 1024; i += 256) {
            int r = i >> 4, dq = (i & 15) * 4;
            float4 v = *(const float4*)(kgb + (size_t)(kt * 64 + r) * HD + dq);
            float4 o4 = make_float4(f2tf32f(v.x), f2tf32f(v.y), f2tf32f(v.z), f2tf32f(v.w));
            *(float4*)&Ks[r * ST + dq] = o4;
        }
        for (int i = tid; i < 1024; i += 256) {
            int d = i >> 4, kq = (i & 15) * 4;
            float4 v = *(const float4*)(vbt + (size_t)d * N_ + kt * 64 + kq);
            float4 o4 = make_float4(f2tf32f(v.x), f2tf32f(v.y), f2tf32f(v.z), f2tf32f(v.w));
            *(float4*)&Vs[d * ST + kq] = o4;
        }
        // bias slab: t = (i-i0)-(j-j0)+63 in [0,190]
        if (tid < 191)
            bsh[tid] = bias_table[(i0 - kt * 64 + 448 + tid) * H_ + h];
        __syncthreads();

        float s[8][4];
#pragma unroll
        for (int nt = 0; nt < 8; nt++)
#pragma unroll
            for (int r = 0; r < 4; r++) s[nt][r] = 0.f;

#pragma unroll
        for (int kb = 0; kb < 8; kb++) {
#pragma unroll
            for (int nt = 0; nt < 8; nt++) {
                unsigned b0 = __float_as_uint(Ks[(nt * 8 + g) * ST + kb * 8 + t]);
                unsigned b1 = __float_as_uint(Ks[(nt * 8 + g) * ST + kb * 8 + t + 4]);
                mma_tf32(s[nt], qa[kb][0], qa[kb][1], qa[kb][2], qa[kb][3], b0, b1);
            }
        }

        float mt2[2] = {-1e30f, -1e30f};
#pragma unroll
        for (int nt = 0; nt < 8; nt++) {
            int jl = nt * 8 + 2 * t;
            s[nt][0] += bsh[(q0 + g) - jl + 63];
            s[nt][1] += bsh[(q0 + g) - jl + 62];
            s[nt][2] += bsh[(q0 + g + 8) - jl + 63];
            s[nt][3] += bsh[(q0 + g + 8) - jl + 62];
            mt2[0] = fmaxf(mt2[0], fmaxf(s[nt][0], s[nt][1]));
            mt2[1] = fmaxf(mt2[1], fmaxf(s[nt][2], s[nt][3]));
        }
        mt2[0] = fmaxf(mt2[0], __shfl_xor_sync(0xffffffffu, mt2[0], 1));
        mt2[0] = fmaxf(mt2[0], __shfl_xor_sync(0xffffffffu, mt2[0], 2));
        mt2[1] = fmaxf(mt2[1], __shfl_xor_sync(0xffffffffu, mt2[1], 1));
        mt2[1] = fmaxf(mt2[1], __shfl_xor_sync(0xffffffffu, mt2[1], 2));

        float mn0 = fmaxf(m_[0], mt2[0]);
        float mn1 = fmaxf(m_[1], mt2[1]);
        float al0 = __expf(m_[0] - mn0);
        float al1 = __expf(m_[1] - mn1);
        m_[0] = mn0; m_[1] = mn1;

        float rs0 = 0.f, rs1 = 0.f;
#pragma unroll
        for (int nt = 0; nt < 8; nt++) {
            s[nt][0] = __expf(s[nt][0] - mn0);
            s[nt][1] = __expf(s[nt][1] - mn0);
            s[nt][2] = __expf(s[nt][2] - mn1);
            s[nt][3] = __expf(s[nt][3] - mn1);
            rs0 += s[nt][0] + s[nt][1];
            rs1 += s[nt][2] + s[nt][3];
        }
        rs0 += __shfl_xor_sync(0xffffffffu, rs0, 1);
        rs0 += __shfl_xor_sync(0xffffffffu, rs0, 2);
        rs1 += __shfl_xor_sync(0xffffffffu, rs1, 1);
        rs1 += __shfl_xor_sync(0xffffffffu, rs1, 2);
        l_[0] = l_[0] * al0 + rs0;
        l_[1] = l_[1] * al1 + rs1;
#pragma unroll
        for (int nt = 0; nt < 8; nt++) {
            o_[nt][0] *= al0; o_[nt][1] *= al0;
            o_[nt][2] *= al1; o_[nt][3] *= al1;
        }

        // store P (tf32) to warp-private rows of Ps
#pragma unroll
        for (int nt = 0; nt < 8; nt++) {
            int col = nt * 8 + 2 * t;
            *(float2*)&Ps[(q0 + g) * ST + col] =
                make_float2(f2tf32f(s[nt][0]), f2tf32f(s[nt][1]));
            *(float2*)&Ps[(q0 + g + 8) * ST + col] =
                make_float2(f2tf32f(s[nt][2]), f2tf32f(s[nt][3]));
        }
        __syncwarp();

#pragma unroll
        for (int kb = 0; kb < 8; kb++) {
            unsigned pa0 = __float_as_uint(Ps[(q0 + g) * ST + kb * 8 + t]);
            unsigned pa1 = __float_as_uint(Ps[(q0 + g + 8) * ST + kb * 8 + t]);
            unsigned pa2 = __float_as_uint(Ps[(q0 + g) * ST + kb * 8 + t + 4]);
            unsigned pa3 = __float_as_uint(Ps[(q0 + g + 8) * ST + kb * 8 + t + 4]);
#pragma unroll
            for (int nt = 0; nt < 8; nt++) {
                unsigned b0 = __float_as_uint(Vs[(nt * 8 + g) * ST + kb * 8 + t]);
                unsigned b1 = __float_as_uint(Vs[(nt * 8 + g) * ST + kb * 8 + t + 4]);
                mma_tf32(o_[nt], pa0, pa1, pa2, pa3, b0, b1);
            }
        }
        __syncthreads();
    }

    // epilogue (tf32-rounded so proj GEMM reads already-rounded operands)
    float inv0 = 1.0f / l_[0];
    float inv1 = 1.0f / l_[1];
    int r0 = i0 + q0 + g;
    int r1 = r0 + 8;
#pragma unroll
    for (int nt = 0; nt < 8; nt++) {
        int col = h * 64 + nt * 8 + 2 * t;
        *(float2*)&g_att[((size_t)(b * N_ + r0)) * C_ + col] =
            make_float2(f2tf32f(o_[nt][0] * inv0), f2tf32f(o_[nt][1] * inv0));
        *(float2*)&g_att[((size_t)(b * N_ + r1)) * C_ + col] =
            make_float2(f2tf32f(o_[nt][2] * inv1), f2tf32f(o_[nt][3] * inv1));
    }
}

// ---------------------------------------------------------------------------
extern "C" void kernel_launch(void* const* d_in, const int* in_sizes, int n_in,
                              void* d_out, int out_size)
{
    const float* x          = (const float*)d_in[0];
    const float* qkv_w      = (const float*)d_in[1];
    const float* proj_w     = (const float*)d_in[2];
    const float* proj_b     = (const float*)d_in[3];
    const float* bias_table = (const float*)d_in[4];
    float* out = (float*)d_out;

    cudaFuncSetAttribute(gemm_tf32<0>,
                         cudaFuncAttributeMaxDynamicSharedMemorySize, SMEM_GEMM);
    cudaFuncSetAttribute(gemm_tf32<1>,
                         cudaFuncAttributeMaxDynamicSharedMemorySize, SMEM_GEMM);
    cudaFuncSetAttribute(attn_kernel,
                         cudaFuncAttributeMaxDynamicSharedMemorySize, SMEM_ATTN);

    // 1) QKV projection: [32768,768] @ [2304,768]^T -> g_qkv (V transposed)
    gemm_tf32<0><<<dim3(2304 / 128, 32768 / 128), 256, SMEM_GEMM>>>(
        x, qkv_w, nullptr, nullptr);

    // 2) attention: 768 (b,h) pairs x 4 q-tiles of 128 rows
    attn_kernel<<<dim3(N_ / 128, B_ * H_), 256, SMEM_ATTN>>>(bias_table);

    // 3) output projection: [32768,768] @ [768,768]^T + bias -> d_out
    gemm_tf32<1><<<dim3(768 / 128, 32768 / 128), 256, SMEM_GEMM>>>(
        nullptr, proj_w, proj_b, out);
}

// round 16
// speedup vs baseline: 1.2282x; 1.2282x over previous
#include <cuda_runtime.h>
#include <math.h>
#include <stdint.h>

#define B_  64
#define N_  512
#define C_  768
#define H_  12
#define HD  64
#define QS  ((size_t)B_ * H_ * N_ * HD)

// Scratch (allocation-free contract -> __device__ globals)
__device__ __align__(16) float g_qkv[3 * QS];                 // Q,K:[b,h,n,d]  V:[b,h,d,n]
__device__ __align__(16) float g_att[(size_t)B_ * N_ * C_];   // attention out (tf32-rounded)
__device__ __align__(16) float g_xr[(size_t)B_ * N_ * C_];    // x rounded to tf32 (RNA)
__device__ __align__(16) float g_wq[(size_t)3 * C_ * C_];     // qkv_w rounded
__device__ __align__(16) float g_wp[(size_t)C_ * C_];         // proj_w rounded

// ---------------------------------------------------------------------------
__device__ __forceinline__ unsigned f2tf32(float f) {
    unsigned r;
    asm("cvt.rna.tf32.f32 %0, %1;" : "=r"(r) : "f"(f));
    return r;
}
__device__ __forceinline__ float f2tf32f(float f) { return __uint_as_float(f2tf32(f)); }

__device__ __forceinline__ void mma_tf32(float c[4],
                                         unsigned a0, unsigned a1, unsigned a2, unsigned a3,
                                         unsigned b0, unsigned b1) {
    asm volatile(
        "mma.sync.aligned.m16n8k8.row.col.f32.tf32.tf32.f32 "
        "{%0,%1,%2,%3}, {%4,%5,%6,%7}, {%8,%9}, {%0,%1,%2,%3};"
        : "+f"(c[0]), "+f"(c[1]), "+f"(c[2]), "+f"(c[3])
        : "r"(a0), "r"(a1), "r"(a2), "r"(a3), "r"(b0), "r"(b1));
}

__device__ __forceinline__ void cp_async16(unsigned dst, const void* src) {
    asm volatile("cp.async.ca.shared.global [%0], [%1], 16;" :: "r"(dst), "l"(src));
}
__device__ __forceinline__ void cp_commit() { asm volatile("cp.async.commit_group;"); }
template<int NW>
__device__ __forceinline__ void cp_wait() {
    asm volatile("cp.async.wait_group %0;" :: "n"(NW));
}

// ---------------------------------------------------------------------------
// tf32 GEMM (R13-proven structure): out = A[M,K] @ W[N,K]^T. CTA 128x128,
// 256 threads = 8 warps (2 M x 4 N), warp tile 64x32. BK=32 two-stage
// cp.async double-buffer, stride-36 smem.
// NEW vs R13: operands are pre-rounded to tf32 (RNA) in g_xr/g_wq/g_wp/g_att,
// so fragment loads are raw bit loads — the 24 CVTs per warp-kb-step vanish
// (64 -> 40 instructions per 16 MMA; the kernel is issue-mix-bound).
// MODE 0: g_xr @ g_wq^T -> scatter g_qkv (V transposed). MODE 1: g_att @ g_wp^T + bias.
// ---------------------------------------------------------------------------
#define GST 36
#define GBUF (128 * GST)
#define SMEM_GEMM (4 * GBUF * 4)     // 73728 B

template<int MODE>
__global__ __launch_bounds__(256, 2)
void gemm_tf32(const float* __restrict__ bias, float* __restrict__ out)
{
    extern __shared__ float smg[];
    float* As = smg;                 // [2][128][36]
    float* Ws = smg + 2 * GBUF;      // [2][128][36]
    const int K = C_;

    const float* Ap = (MODE == 1) ? (const float*)g_att : (const float*)g_xr;
    const float* Wp = (MODE == 1) ? (const float*)g_wp  : (const float*)g_wq;

    int m0 = blockIdx.y * 128;
    int n0 = blockIdx.x * 128;
    int tid = threadIdx.x;
    int lane = tid & 31, warp = tid >> 5;
    int wm = warp & 1;            // 2 M-halves of 64
    int wn = warp >> 1;           // 4 N-quarters of 32
    int g = lane >> 2, t = lane & 3;

    unsigned sbase = (unsigned)__cvta_generic_to_shared(smg);

    float acc[4][4][4];
#pragma unroll
    for (int mt = 0; mt < 4; mt++)
#pragma unroll
        for (int nt = 0; nt < 4; nt++)
#pragma unroll
            for (int r = 0; r < 4; r++) acc[mt][nt][r] = 0.f;

    int lr = tid >> 3;            // 0..31
    int lkq = (tid & 7) * 4;      // 0..28

    const int NS = K / 32;        // 24

    auto stage = [&](int s, int buf) {
        int k0 = s * 32;
#pragma unroll
        for (int p = 0; p < 4; p++) {
            int r = p * 32 + lr;
            unsigned dA = sbase + (unsigned)((buf * GBUF + r * GST + lkq) * 4);
            unsigned dW = sbase + (unsigned)((2 * GBUF + buf * GBUF + r * GST + lkq) * 4);
            cp_async16(dA, Ap + (size_t)(m0 + r) * K + k0 + lkq);
            cp_async16(dW, Wp + (size_t)(n0 + r) * K + k0 + lkq);
        }
    };

    stage(0, 0);
    cp_commit();

    for (int s = 0; s < NS; s++) {
        if (s + 1 < NS) {
            stage(s + 1, (s + 1) & 1);
            cp_commit();
            cp_wait<1>();
        } else {
            cp_wait<0>();
        }
        __syncthreads();

        const float* Ab = As + (s & 1) * GBUF;
        const float* Wb = Ws + (s & 1) * GBUF;

#pragma unroll
        for (int kb = 0; kb < 32; kb += 8) {
            unsigned a[4][4];
#pragma unroll
            for (int mt = 0; mt < 4; mt++) {
                int r = wm * 64 + mt * 16 + g;
                a[mt][0] = __float_as_uint(Ab[r * GST + kb + t]);
                a[mt][1] = __float_as_uint(Ab[(r + 8) * GST + kb + t]);
                a[mt][2] = __float_as_uint(Ab[r * GST + kb + t + 4]);
                a[mt][3] = __float_as_uint(Ab[(r + 8) * GST + kb + t + 4]);
            }
#pragma unroll
            for (int nt = 0; nt < 4; nt++) {
                int c = wn * 32 + nt * 8 + g;
                unsigned b0 = __float_as_uint(Wb[c * GST + kb + t]);
                unsigned b1 = __float_as_uint(Wb[c * GST + kb + t + 4]);
#pragma unroll
                for (int mt = 0; mt < 4; mt++)
                    mma_tf32(acc[mt][nt], a[mt][0], a[mt][1], a[mt][2], a[mt][3], b0, b1);
            }
        }
        __syncthreads();
    }

    // epilogue: c-frag rows g,g+8; cols 2t,2t+1
#pragma unroll
    for (int mt = 0; mt < 4; mt++) {
#pragma unroll
        for (int nt = 0; nt < 4; nt++) {
            int n = n0 + wn * 32 + nt * 8 + 2 * t;
#pragma unroll
            for (int half = 0; half < 2; half++) {
                int m = m0 + wm * 64 + mt * 16 + g + half * 8;
                float2 val = make_float2(acc[mt][nt][half * 2],
                                         acc[mt][nt][half * 2 + 1]);
                if (MODE == 0) {
                    int which = n / C_;
                    int rem = n - which * C_;
                    int h = rem >> 6;
                    int d = rem & 63;
                    int b = m >> 9;
                    int nn = m & 511;
                    if (which < 2) {
                        float* dst = g_qkv + (size_t)which * QS
                                   + (((size_t)(b * H_ + h) * N_ + nn) * HD) + d;
                        *(float2*)dst = val;
                    } else {
                        // V transposed: [b][h][d][n]
                        float* dst = g_qkv + 2 * QS
                                   + ((size_t)(b * H_ + h) * HD + d) * N_ + nn;
                        dst[0] = val.x;
                        dst[N_] = val.y;
                    }
                } else {
                    val.x += bias[n];
                    val.y += bias[n + 1];
                    *(float2*)(out + (size_t)m * C_ + n) = val;
                }
            }
        }
    }
}

// ---------------------------------------------------------------------------
// Round inputs to tf32 (RNA) once — SCALAR accesses (proven safe in R12).
// ---------------------------------------------------------------------------
__global__ void cvt_all(const float* __restrict__ x,
                        const float* __restrict__ wq,
                        const float* __restrict__ wp)
{
    const int NX = B_ * N_ * C_;
    const int NQ = 3 * C_ * C_;
    const int NP = C_ * C_;
    int i = blockIdx.x * blockDim.x + threadIdx.x;
    if (i < NX)                g_xr[i] = f2tf32f(x[i]);
    else if (i < NX + NQ)      g_wq[i - NX] = f2tf32f(wq[i - NX]);
    else if (i < NX + NQ + NP) g_wp[i - NX - NQ] = f2tf32f(wp[i - NX - NQ]);
}

// ---------------------------------------------------------------------------
// tf32 tensor-core flash attention (R7/R13-proven v1: 64-row q-tiles,
// 128 threads). Output tf32-rounded so gemm<1> reads pre-rounded operands.
// ---------------------------------------------------------------------------
__global__ __launch_bounds__(128)
void attn_kernel(const float* __restrict__ bias_table)
{
    const int ST = 68;
    extern __shared__ float sm[];
    float* Ks  = sm;               // [64][68]  Ks[key][d]
    float* Vs  = Ks + 64 * ST;     // [64][68]  Vs[d][key]
    float* Ps  = Vs + 64 * ST;     // [64][68]  Ps[q][key]; also Q staging
    float* bsh = Ps + 64 * ST;     // [128]

    int bh = blockIdx.y;
    int b = bh / H_;
    int h = bh - b * H_;
    int i0 = blockIdx.x * 64;

    const float* qb  = g_qkv + (size_t)bh * N_ * HD;
    const float* kgb = qb + QS;
    const float* vbt = g_qkv + 2 * QS + (size_t)bh * HD * N_;  // [d][n]

    int tid = threadIdx.x;
    int lane = tid & 31, warp = tid >> 5;
    int g = lane >> 2, t = lane & 3;
    int q0 = warp * 16;

    for (int i = tid; i < 1024; i += 128) {
        int r = i >> 4, dq = (i & 15) * 4;
        *(float4*)&Ps[r * ST + dq] = *(const float4*)(qb + (size_t)(i0 + r) * HD + dq);
    }
    __syncthreads();

    unsigned qa[8][4];
#pragma unroll
    for (int kb = 0; kb < 8; kb++) {
        qa[kb][0] = f2tf32(0.125f * Ps[(q0 + g) * ST + kb * 8 + t]);
        qa[kb][1] = f2tf32(0.125f * Ps[(q0 + g + 8) * ST + kb * 8 + t]);
        qa[kb][2] = f2tf32(0.125f * Ps[(q0 + g) * ST + kb * 8 + t + 4]);
        qa[kb][3] = f2tf32(0.125f * Ps[(q0 + g + 8) * ST + kb * 8 + t + 4]);
    }
    __syncthreads();

    float m_[2] = {-1e30f, -1e30f};
    float l_[2] = {0.f, 0.f};
    float o_[8][4];
#pragma unroll
    for (int nt = 0; nt < 8; nt++)
#pragma unroll
        for (int r = 0; r < 4; r++) o_[nt][r] = 0.f;

    for (int kt = 0; kt < 8; kt++) {
        for (int i = tid; i < 1024; i += 128) {
            int r = i >> 4, dq = (i & 15) * 4;
            float4 v = *(const float4*)(kgb + (size_t)(kt * 64 + r) * HD + dq);
            float4 o4 = make_float4(f2tf32f(v.x), f2tf32f(v.y), f2tf32f(v.z), f2tf32f(v.w));
            *(float4*)&Ks[r * ST + dq] = o4;
        }
        for (int i = tid; i < 1024; i += 128) {
            int d = i >> 4, kq = (i & 15) * 4;
            float4 v = *(const float4*)(vbt + (size_t)d * N_ + kt * 64 + kq);
            float4 o4 = make_float4(f2tf32f(v.x), f2tf32f(v.y), f2tf32f(v.z), f2tf32f(v.w));
            *(float4*)&Vs[d * ST + kq] = o4;
        }
        if (tid < 127)
            bsh[tid] = bias_table[(i0 - kt * 64 + 448 + tid) * H_ + h];
        __syncthreads();

        float s[8][4];
#pragma unroll
        for (int nt = 0; nt < 8; nt++)
#pragma unroll
            for (int r = 0; r < 4; r++) s[nt][r] = 0.f;

#pragma unroll
        for (int kb = 0; kb < 8; kb++) {
#pragma unroll
            for (int nt = 0; nt < 8; nt++) {
                unsigned b0 = __float_as_uint(Ks[(nt * 8 + g) * ST + kb * 8 + t]);
                unsigned b1 = __float_as_uint(Ks[(nt * 8 + g) * ST + kb * 8 + t + 4]);
                mma_tf32(s[nt], qa[kb][0], qa[kb][1], qa[kb][2], qa[kb][3], b0, b1);
            }
        }

        float mt2[2] = {-1e30f, -1e30f};
#pragma unroll
        for (int nt = 0; nt < 8; nt++) {
            int jl = nt * 8 + 2 * t;
            s[nt][0] += bsh[(q0 + g) - jl + 63];
            s[nt][1] += bsh[(q0 + g) - jl + 62];
            s[nt][2] += bsh[(q0 + g + 8) - jl + 63];
            s[nt][3] += bsh[(q0 + g + 8) - jl + 62];
            mt2[0] = fmaxf(mt2[0], fmaxf(s[nt][0], s[nt][1]));
            mt2[1] = fmaxf(mt2[1], fmaxf(s[nt][2], s[nt][3]));
        }
        mt2[0] = fmaxf(mt2[0], __shfl_xor_sync(0xffffffffu, mt2[0], 1));
        mt2[0] = fmaxf(mt2[0], __shfl_xor_sync(0xffffffffu, mt2[0], 2));
        mt2[1] = fmaxf(mt2[1], __shfl_xor_sync(0xffffffffu, mt2[1], 1));
        mt2[1] = fmaxf(mt2[1], __shfl_xor_sync(0xffffffffu, mt2[1], 2));

        float mn0 = fmaxf(m_[0], mt2[0]);
        float mn1 = fmaxf(m_[1], mt2[1]);
        float al0 = __expf(m_[0] - mn0);
        float al1 = __expf(m_[1] - mn1);
        m_[0] = mn0; m_[1] = mn1;

        float rs0 = 0.f, rs1 = 0.f;
#pragma unroll
        for (int nt = 0; nt < 8; nt++) {
            s[nt][0] = __expf(s[nt][0] - mn0);
            s[nt][1] = __expf(s[nt][1] - mn0);
            s[nt][2] = __expf(s[nt][2] - mn1);
            s[nt][3] = __expf(s[nt][3] - mn1);
            rs0 += s[nt][0] + s[nt][1];
            rs1 += s[nt][2] + s[nt][3];
        }
        rs0 += __shfl_xor_sync(0xffffffffu, rs0, 1);
        rs0 += __shfl_xor_sync(0xffffffffu, rs0, 2);
        rs1 += __shfl_xor_sync(0xffffffffu, rs1, 1);
        rs1 += __shfl_xor_sync(0xffffffffu, rs1, 2);
        l_[0] = l_[0] * al0 + rs0;
        l_[1] = l_[1] * al1 + rs1;
#pragma unroll
        for (int nt = 0; nt < 8; nt++) {
            o_[nt][0] *= al0; o_[nt][1] *= al0;
            o_[nt][2] *= al1; o_[nt][3] *= al1;
        }

#pragma unroll
        for (int nt = 0; nt < 8; nt++) {
            int col = nt * 8 + 2 * t;
            *(float2*)&Ps[(q0 + g) * ST + col] =
                make_float2(f2tf32f(s[nt][0]), f2tf32f(s[nt][1]));
            *(float2*)&Ps[(q0 + g + 8) * ST + col] =
                make_float2(f2tf32f(s[nt][2]), f2tf32f(s[nt][3]));
        }
        __syncwarp();

#pragma unroll
        for (int kb = 0; kb < 8; kb++) {
            unsigned pa0 = __float_as_uint(Ps[(q0 + g) * ST + kb * 8 + t]);
            unsigned pa1 = __float_as_uint(Ps[(q0 + g + 8) * ST + kb * 8 + t]);
            unsigned pa2 = __float_as_uint(Ps[(q0 + g) * ST + kb * 8 + t + 4]);
            unsigned pa3 = __float_as_uint(Ps[(q0 + g + 8) * ST + kb * 8 + t + 4]);
#pragma unroll
            for (int nt = 0; nt < 8; nt++) {
                unsigned b0 = __float_as_uint(Vs[(nt * 8 + g) * ST + kb * 8 + t]);
                unsigned b1 = __float_as_uint(Vs[(nt * 8 + g) * ST + kb * 8 + t + 4]);
                mma_tf32(o_[nt], pa0, pa1, pa2, pa3, b0, b1);
            }
        }
        __syncthreads();
    }

    // epilogue (tf32-rounded so proj GEMM reads already-rounded operands)
    float inv0 = 1.0f / l_[0];
    float inv1 = 1.0f / l_[1];
    int r0 = i0 + q0 + g;
    int r1 = r0 + 8;
#pragma unroll
    for (int nt = 0; nt < 8; nt++) {
        int col = h * 64 + nt * 8 + 2 * t;
        *(float2*)&g_att[((size_t)(b * N_ + r0)) * C_ + col] =
            make_float2(f2tf32f(o_[nt][0] * inv0), f2tf32f(o_[nt][1] * inv0));
        *(float2*)&g_att[((size_t)(b * N_ + r1)) * C_ + col] =
            make_float2(f2tf32f(o_[nt][2] * inv1), f2tf32f(o_[nt][3] * inv1));
    }
}

// ---------------------------------------------------------------------------
extern "C" void kernel_launch(void* const* d_in, const int* in_sizes, int n_in,
                              void* d_out, int out_size)
{
    const float* x          = (const float*)d_in[0];
    const float* qkv_w      = (const float*)d_in[1];
    const float* proj_w     = (const float*)d_in[2];
    const float* proj_b     = (const float*)d_in[3];
    const float* bias_table = (const float*)d_in[4];
    float* out = (float*)d_out;

    const int smem_attn = (3 * 64 * 68 + 128) * sizeof(float);   // 52736 B

    cudaFuncSetAttribute(gemm_tf32<0>,
                         cudaFuncAttributeMaxDynamicSharedMemorySize, SMEM_GEMM);
    cudaFuncSetAttribute(gemm_tf32<1>,
                         cudaFuncAttributeMaxDynamicSharedMemorySize, SMEM_GEMM);
    cudaFuncSetAttribute(attn_kernel,
                         cudaFuncAttributeMaxDynamicSharedMemorySize, smem_attn);

    // 0) round inputs to tf32 once (scalar, RNA)
    int total = B_ * N_ * C_ + 3 * C_ * C_ + C_ * C_;
    cvt_all<<<(total + 255) / 256, 256>>>(x, qkv_w, proj_w);

    // 1) QKV projection: [32768,768] @ [2304,768]^T -> g_qkv (V transposed)
    gemm_tf32<0><<<dim3(2304 / 128, 32768 / 128), 256, SMEM_GEMM>>>(nullptr, nullptr);

    // 2) attention: 768 (b,h) pairs x 8 query tiles of 64 rows
    attn_kernel<<<dim3(N_ / 64, B_ * H_), 128, smem_attn>>>(bias_table);

    // 3) output projection: [32768,768] @ [768,768]^T + bias -> d_out
    gemm_tf32<1><<<dim3(768 / 128, 32768 / 128), 256, SMEM_GEMM>>>(proj_b, out);
}

// round 17
// speedup vs baseline: 1.5748x; 1.2823x over previous
#include <cuda_runtime.h>
#include <cuda_fp16.h>
#include <math.h>
#include <stdint.h>

#define B_  64
#define N_  512
#define C_  768
#define H_  12
#define HD  64
#define QS  ((size_t)B_ * H_ * N_ * HD)

// Scratch (allocation-free contract -> __device__ globals)
__device__ __align__(16) float  g_qkv[3 * QS];                  // Q,K:[b,h,n,d]  V:[b,h,d,n] (fp32)
__device__ __align__(16) __half g_ath[(size_t)B_ * N_ * C_];    // attention out (fp16)
__device__ __align__(16) __half g_xh[(size_t)B_ * N_ * C_];     // x  -> fp16
__device__ __align__(16) __half g_wqh[(size_t)3 * C_ * C_];     // qkv_w -> fp16
__device__ __align__(16) __half g_wph[(size_t)C_ * C_];         // proj_w -> fp16

// ---------------------------------------------------------------------------
__device__ __forceinline__ unsigned f2tf32(float f) {
    unsigned r;
    asm("cvt.rna.tf32.f32 %0, %1;" : "=r"(r) : "f"(f));
    return r;
}
__device__ __forceinline__ float f2tf32f(float f) { return __uint_as_float(f2tf32(f)); }

__device__ __forceinline__ void mma_tf32(float c[4],
                                         unsigned a0, unsigned a1, unsigned a2, unsigned a3,
                                         unsigned b0, unsigned b1) {
    asm volatile(
        "mma.sync.aligned.m16n8k8.row.col.f32.tf32.tf32.f32 "
        "{%0,%1,%2,%3}, {%4,%5,%6,%7}, {%8,%9}, {%0,%1,%2,%3};"
        : "+f"(c[0]), "+f"(c[1]), "+f"(c[2]), "+f"(c[3])
        : "r"(a0), "r"(a1), "r"(a2), "r"(a3), "r"(b0), "r"(b1));
}

__device__ __forceinline__ void mma_f16(float c[4],
                                        unsigned a0, unsigned a1, unsigned a2, unsigned a3,
                                        unsigned b0, unsigned b1) {
    asm volatile(
        "mma.sync.aligned.m16n8k16.row.col.f32.f16.f16.f32 "
        "{%0,%1,%2,%3}, {%4,%5,%6,%7}, {%8,%9}, {%0,%1,%2,%3};"
        : "+f"(c[0]), "+f"(c[1]), "+f"(c[2]), "+f"(c[3])
        : "r"(a0), "r"(a1), "r"(a2), "r"(a3), "r"(b0), "r"(b1));
}

__device__ __forceinline__ void cp_async16(unsigned dst, const void* src) {
    asm volatile("cp.async.ca.shared.global [%0], [%1], 16;" :: "r"(dst), "l"(src));
}
__device__ __forceinline__ void cp_commit() { asm volatile("cp.async.commit_group;"); }
template<int NW>
__device__ __forceinline__ void cp_wait() {
    asm volatile("cp.async.wait_group %0;" :: "n"(NW));
}

// ---------------------------------------------------------------------------
// fp16 GEMM: out = A[M,K] @ W[N,K]^T, fp16 operands, fp32 accum.
// CTA 128x128, 256 threads = 8 warps (2 M x 4 N), warp tile 64x32.
// BK=32 (2 x k16 mma steps), cp.async double-buffer, stride-40-half smem
// (banks: (g*20+t) mod 32 all distinct -> conflict-free fragment loads).
// MODE 0: g_xh @ g_wqh^T -> scatter fp32 g_qkv (V transposed).
// MODE 1: g_ath @ g_wph^T + bias -> fp32 out.
// ---------------------------------------------------------------------------
#define GSTH 40
#define GBUFH (128 * GSTH)
#define SMEM_GEMM (8 * GBUFH)        // bytes: 2 bufs x (A+B) x 128x40 halves = 40960

template<int MODE>
__global__ __launch_bounds__(256, 2)
void gemm_f16(const float* __restrict__ bias, float* __restrict__ out)
{
    extern __shared__ __half smh[];
    __half* As = smh;                  // [2][128][40]
    __half* Ws = smh + 2 * GBUFH;      // [2][128][40]
    const int K = C_;

    const __half* Ap = (MODE == 1) ? (const __half*)g_ath : (const __half*)g_xh;
    const __half* Wp = (MODE == 1) ? (const __half*)g_wph : (const __half*)g_wqh;

    int m0 = blockIdx.y * 128;
    int n0 = blockIdx.x * 128;
    int tid = threadIdx.x;
    int lane = tid & 31, warp = tid >> 5;
    int wm = warp & 1;            // 2 M-halves of 64
    int wn = warp >> 1;           // 4 N-quarters of 32
    int g = lane >> 2, t = lane & 3;

    unsigned sbase = (unsigned)__cvta_generic_to_shared(smh);

    float acc[4][4][4];
#pragma unroll
    for (int mt = 0; mt < 4; mt++)
#pragma unroll
        for (int nt = 0; nt < 4; nt++)
#pragma unroll
            for (int r = 0; r < 4; r++) acc[mt][nt][r] = 0.f;

    int lrow = tid >> 2;          // 0..63
    int lkc  = (tid & 3) * 8;     // half-offset of 16B chunk within 32-half row

    const int NS = K / 32;        // 24

    auto stage = [&](int s, int buf) {
        int k0 = s * 32;
#pragma unroll
        for (int p = 0; p < 2; p++) {
            int r = p * 64 + lrow;
            unsigned dA = sbase + (unsigned)((buf * GBUFH + r * GSTH + lkc) * 2);
            unsigned dW = sbase + (unsigned)((2 * GBUFH + buf * GBUFH + r * GSTH + lkc) * 2);
            cp_async16(dA, Ap + (size_t)(m0 + r) * K + k0 + lkc);
            cp_async16(dW, Wp + (size_t)(n0 + r) * K + k0 + lkc);
        }
    };

    stage(0, 0);
    cp_commit();

    for (int s = 0; s < NS; s++) {
        if (s + 1 < NS) {
            stage(s + 1, (s + 1) & 1);
            cp_commit();
            cp_wait<1>();
        } else {
            cp_wait<0>();
        }
        __syncthreads();

        const __half* Ab = As + (s & 1) * GBUFH;
        const __half* Wb = Ws + (s & 1) * GBUFH;

#pragma unroll
        for (int ks = 0; ks < 2; ks++) {       // 2 x k16 per BK=32
            int kb = ks * 16;
            unsigned a[4][4];
#pragma unroll
            for (int mt = 0; mt < 4; mt++) {
                int r = wm * 64 + mt * 16 + g;
                a[mt][0] = *(const unsigned*)&Ab[r * GSTH + kb + 2 * t];
                a[mt][1] = *(const unsigned*)&Ab[(r + 8) * GSTH + kb + 2 * t];
                a[mt][2] = *(const unsigned*)&Ab[r * GSTH + kb + 2 * t + 8];
                a[mt][3] = *(const unsigned*)&Ab[(r + 8) * GSTH + kb + 2 * t + 8];
            }
#pragma unroll
            for (int nt = 0; nt < 4; nt++) {
                int c = wn * 32 + nt * 8 + g;
                unsigned b0 = *(const unsigned*)&Wb[c * GSTH + kb + 2 * t];
                unsigned b1 = *(const unsigned*)&Wb[c * GSTH + kb + 2 * t + 8];
#pragma unroll
                for (int mt = 0; mt < 4; mt++)
                    mma_f16(acc[mt][nt], a[mt][0], a[mt][1], a[mt][2], a[mt][3], b0, b1);
            }
        }
        __syncthreads();
    }

    // epilogue: c-frag rows g,g+8; cols 2t,2t+1
#pragma unroll
    for (int mt = 0; mt < 4; mt++) {
#pragma unroll
        for (int nt = 0; nt < 4; nt++) {
            int n = n0 + wn * 32 + nt * 8 + 2 * t;
#pragma unroll
            for (int half = 0; half < 2; half++) {
                int m = m0 + wm * 64 + mt * 16 + g + half * 8;
                float2 val = make_float2(acc[mt][nt][half * 2],
                                         acc[mt][nt][half * 2 + 1]);
                if (MODE == 0) {
                    int which = n / C_;
                    int rem = n - which * C_;
                    int h = rem >> 6;
                    int d = rem & 63;
                    int b = m >> 9;
                    int nn = m & 511;
                    if (which < 2) {
                        float* dst = g_qkv + (size_t)which * QS
                                   + (((size_t)(b * H_ + h) * N_ + nn) * HD) + d;
                        *(float2*)dst = val;
                    } else {
                        // V transposed: [b][h][d][n]
                        float* dst = g_qkv + 2 * QS
                                   + ((size_t)(b * H_ + h) * HD + d) * N_ + nn;
                        dst[0] = val.x;
                        dst[N_] = val.y;
                    }
                } else {
                    val.x += bias[n];
                    val.y += bias[n + 1];
                    *(float2*)(out + (size_t)m * C_ + n) = val;
                }
            }
        }
    }
}

// ---------------------------------------------------------------------------
// Convert inputs to fp16 once — SCALAR accesses (alignment-immune).
// ---------------------------------------------------------------------------
__global__ void cvt_all(const float* __restrict__ x,
                        const float* __restrict__ wq,
                        const float* __restrict__ wp)
{
    const int NX = B_ * N_ * C_;
    const int NQ = 3 * C_ * C_;
    const int NP = C_ * C_;
    int i = blockIdx.x * blockDim.x + threadIdx.x;
    if (i < NX)                g_xh[i] = __float2half_rn(x[i]);
    else if (i < NX + NQ)      g_wqh[i - NX] = __float2half_rn(wq[i - NX]);
    else if (i < NX + NQ + NP) g_wph[i - NX - NQ] = __float2half_rn(wp[i - NX - NQ]);
}

// ---------------------------------------------------------------------------
// tf32 tensor-core flash attention (R16-proven). Epilogue now emits fp16
// into g_ath for the fp16 proj GEMM.
// ---------------------------------------------------------------------------
__global__ __launch_bounds__(128)
void attn_kernel(const float* __restrict__ bias_table)
{
    const int ST = 68;
    extern __shared__ float sm[];
    float* Ks  = sm;               // [64][68]  Ks[key][d]
    float* Vs  = Ks + 64 * ST;     // [64][68]  Vs[d][key]
    float* Ps  = Vs + 64 * ST;     // [64][68]  Ps[q][key]; also Q staging
    float* bsh = Ps + 64 * ST;     // [128]

    int bh = blockIdx.y;
    int b = bh / H_;
    int h = bh - b * H_;
    int i0 = blockIdx.x * 64;

    const float* qb  = g_qkv + (size_t)bh * N_ * HD;
    const float* kgb = qb + QS;
    const float* vbt = g_qkv + 2 * QS + (size_t)bh * HD * N_;  // [d][n]

    int tid = threadIdx.x;
    int lane = tid & 31, warp = tid >> 5;
    int g = lane >> 2, t = lane & 3;
    int q0 = warp * 16;

    for (int i = tid; i < 1024; i += 128) {
        int r = i >> 4, dq = (i & 15) * 4;
        *(float4*)&Ps[r * ST + dq] = *(const float4*)(qb + (size_t)(i0 + r) * HD + dq);
    }
    __syncthreads();

    unsigned qa[8][4];
#pragma unroll
    for (int kb = 0; kb < 8; kb++) {
        qa[kb][0] = f2tf32(0.125f * Ps[(q0 + g) * ST + kb * 8 + t]);
        qa[kb][1] = f2tf32(0.125f * Ps[(q0 + g + 8) * ST + kb * 8 + t]);
        qa[kb][2] = f2tf32(0.125f * Ps[(q0 + g) * ST + kb * 8 + t + 4]);
        qa[kb][3] = f2tf32(0.125f * Ps[(q0 + g + 8) * ST + kb * 8 + t + 4]);
    }
    __syncthreads();

    float m_[2] = {-1e30f, -1e30f};
    float l_[2] = {0.f, 0.f};
    float o_[8][4];
#pragma unroll
    for (int nt = 0; nt < 8; nt++)
#pragma unroll
        for (int r = 0; r < 4; r++) o_[nt][r] = 0.f;

    for (int kt = 0; kt < 8; kt++) {
        for (int i = tid; i < 1024; i += 128) {
            int r = i >> 4, dq = (i & 15) * 4;
            float4 v = *(const float4*)(kgb + (size_t)(kt * 64 + r) * HD + dq);
            float4 o4 = make_float4(f2tf32f(v.x), f2tf32f(v.y), f2tf32f(v.z), f2tf32f(v.w));
            *(float4*)&Ks[r * ST + dq] = o4;
        }
        for (int i = tid; i < 1024; i += 128) {
            int d = i >> 4, kq = (i & 15) * 4;
            float4 v = *(const float4*)(vbt + (size_t)d * N_ + kt * 64 + kq);
            float4 o4 = make_float4(f2tf32f(v.x), f2tf32f(v.y), f2tf32f(v.z), f2tf32f(v.w));
            *(float4*)&Vs[d * ST + kq] = o4;
        }
        if (tid < 127)
            bsh[tid] = bias_table[(i0 - kt * 64 + 448 + tid) * H_ + h];
        __syncthreads();

        float s[8][4];
#pragma unroll
        for (int nt = 0; nt < 8; nt++)
#pragma unroll
            for (int r = 0; r < 4; r++) s[nt][r] = 0.f;

#pragma unroll
        for (int kb = 0; kb < 8; kb++) {
#pragma unroll
            for (int nt = 0; nt < 8; nt++) {
                unsigned b0 = __float_as_uint(Ks[(nt * 8 + g) * ST + kb * 8 + t]);
                unsigned b1 = __float_as_uint(Ks[(nt * 8 + g) * ST + kb * 8 + t + 4]);
                mma_tf32(s[nt], qa[kb][0], qa[kb][1], qa[kb][2], qa[kb][3], b0, b1);
            }
        }

        float mt2[2] = {-1e30f, -1e30f};
#pragma unroll
        for (int nt = 0; nt < 8; nt++) {
            int jl = nt * 8 + 2 * t;
            s[nt][0] += bsh[(q0 + g) - jl + 63];
            s[nt][1] += bsh[(q0 + g) - jl + 62];
            s[nt][2] += bsh[(q0 + g + 8) - jl + 63];
            s[nt][3] += bsh[(q0 + g + 8) - jl + 62];
            mt2[0] = fmaxf(mt2[0], fmaxf(s[nt][0], s[nt][1]));
            mt2[1] = fmaxf(mt2[1], fmaxf(s[nt][2], s[nt][3]));
        }
        mt2[0] = fmaxf(mt2[0], __shfl_xor_sync(0xffffffffu, mt2[0], 1));
        mt2[0] = fmaxf(mt2[0], __shfl_xor_sync(0xffffffffu, mt2[0], 2));
        mt2[1] = fmaxf(mt2[1], __shfl_xor_sync(0xffffffffu, mt2[1], 1));
        mt2[1] = fmaxf(mt2[1], __shfl_xor_sync(0xffffffffu, mt2[1], 2));

        float mn0 = fmaxf(m_[0], mt2[0]);
        float mn1 = fmaxf(m_[1], mt2[1]);
        float al0 = __expf(m_[0] - mn0);
        float al1 = __expf(m_[1] - mn1);
        m_[0] = mn0; m_[1] = mn1;

        float rs0 = 0.f, rs1 = 0.f;
#pragma unroll
        for (int nt = 0; nt < 8; nt++) {
            s[nt][0] = __expf(s[nt][0] - mn0);
            s[nt][1] = __expf(s[nt][1] - mn0);
            s[nt][2] = __expf(s[nt][2] - mn1);
            s[nt][3] = __expf(s[nt][3] - mn1);
            rs0 += s[nt][0] + s[nt][1];
            rs1 += s[nt][2] + s[nt][3];
        }
        rs0 += __shfl_xor_sync(0xffffffffu, rs0, 1);
        rs0 += __shfl_xor_sync(0xffffffffu, rs0, 2);
        rs1 += __shfl_xor_sync(0xffffffffu, rs1, 1);
        rs1 += __shfl_xor_sync(0xffffffffu, rs1, 2);
        l_[0] = l_[0] * al0 + rs0;
        l_[1] = l_[1] * al1 + rs1;
#pragma unroll
        for (int nt = 0; nt < 8; nt++) {
            o_[nt][0] *= al0; o_[nt][1] *= al0;
            o_[nt][2] *= al1; o_[nt][3] *= al1;
        }

#pragma unroll
        for (int nt = 0; nt < 8; nt++) {
            int col = nt * 8 + 2 * t;
            *(float2*)&Ps[(q0 + g) * ST + col] =
                make_float2(f2tf32f(s[nt][0]), f2tf32f(s[nt][1]));
            *(float2*)&Ps[(q0 + g + 8) * ST + col] =
                make_float2(f2tf32f(s[nt][2]), f2tf32f(s[nt][3]));
        }
        __syncwarp();

#pragma unroll
        for (int kb = 0; kb < 8; kb++) {
            unsigned pa0 = __float_as_uint(Ps[(q0 + g) * ST + kb * 8 + t]);
            unsigned pa1 = __float_as_uint(Ps[(q0 + g + 8) * ST + kb * 8 + t]);
            unsigned pa2 = __float_as_uint(Ps[(q0 + g) * ST + kb * 8 + t + 4]);
            unsigned pa3 = __float_as_uint(Ps[(q0 + g + 8) * ST + kb * 8 + t + 4]);
#pragma unroll
            for (int nt = 0; nt < 8; nt++) {
                unsigned b0 = __float_as_uint(Vs[(nt * 8 + g) * ST + kb * 8 + t]);
                unsigned b1 = __float_as_uint(Vs[(nt * 8 + g) * ST + kb * 8 + t + 4]);
                mma_tf32(o_[nt], pa0, pa1, pa2, pa3, b0, b1);
            }
        }
        __syncthreads();
    }

    // epilogue: fp16 output for the fp16 proj GEMM
    float inv0 = 1.0f / l_[0];
    float inv1 = 1.0f / l_[1];
    int r0 = i0 + q0 + g;
    int r1 = r0 + 8;
#pragma unroll
    for (int nt = 0; nt < 8; nt++) {
        int col = h * 64 + nt * 8 + 2 * t;
        *(__half2*)&g_ath[((size_t)(b * N_ + r0)) * C_ + col] =
            __floats2half2_rn(o_[nt][0] * inv0, o_[nt][1] * inv0);
        *(__half2*)&g_ath[((size_t)(b * N_ + r1)) * C_ + col] =
            __floats2half2_rn(o_[nt][2] * inv1, o_[nt][3] * inv1);
    }
}

// ---------------------------------------------------------------------------
extern "C" void kernel_launch(void* const* d_in, const int* in_sizes, int n_in,
                              void* d_out, int out_size)
{
    const float* x          = (const float*)d_in[0];
    const float* qkv_w      = (const float*)d_in[1];
    const float* proj_w     = (const float*)d_in[2];
    const float* proj_b     = (const float*)d_in[3];
    const float* bias_table = (const float*)d_in[4];
    float* out = (float*)d_out;

    const int smem_attn = (3 * 64 * 68 + 128) * sizeof(float);   // 52736 B

    cudaFuncSetAttribute(gemm_f16<0>,
                         cudaFuncAttributeMaxDynamicSharedMemorySize, SMEM_GEMM);
    cudaFuncSetAttribute(gemm_f16<1>,
                         cudaFuncAttributeMaxDynamicSharedMemorySize, SMEM_GEMM);
    cudaFuncSetAttribute(attn_kernel,
                         cudaFuncAttributeMaxDynamicSharedMemorySize, smem_attn);

    // 0) convert inputs to fp16 once (scalar)
    int total = B_ * N_ * C_ + 3 * C_ * C_ + C_ * C_;
    cvt_all<<<(total + 255) / 256, 256>>>(x, qkv_w, proj_w);

    // 1) QKV projection (fp16 mma): [32768,768] @ [2304,768]^T -> fp32 g_qkv
    gemm_f16<0><<<dim3(2304 / 128, 32768 / 128), 256, SMEM_GEMM>>>(nullptr, nullptr);

    // 2) attention (tf32): 768 (b,h) pairs x 8 query tiles of 64 rows
    attn_kernel<<<dim3(N_ / 64, B_ * H_), 128, smem_attn>>>(bias_table);

    // 3) output projection (fp16 mma): [32768,768] @ [768,768]^T + bias -> d_out
    gemm_f16<1><<<dim3(768 / 128, 32768 / 128), 256, SMEM_GEMM>>>(proj_b, out);
}